// round 2
// baseline (speedup 1.0000x reference)
#include <cuda_runtime.h>

// Fixed problem shape
#define BB   4
#define CC   256
#define HH   128
#define WW   256
#define NGRP 4
#define CG   64     // channels per group
#define WIN  9      // 1x9 window
#define CK   16     // channel chunk in smem
#define SRS  272    // padded smem row stride (floats): cols -4..259 used, stride chosen for conflict-free LDS.64

__global__ __launch_bounds__(256, 3)
void crestereo_corr_kernel(const float* __restrict__ left,
                           const float* __restrict__ right,
                           const float* __restrict__ flow,
                           float* __restrict__ out)
{
    __shared__ __align__(16) float srw[CK][SRS];  // warped right row, p = col+4 (replicate-padded)
    __shared__ __align__(16) float slf[CK][SRS];  // left row, direct col index

    const int bx = blockIdx.x;
    const int g  = bx & (NGRP - 1);
    const int h  = (bx >> 2) & (HH - 1);
    const int b  = bx >> 9;
    const int t  = threadIdx.x;
    const int w  = t;
    const int HW = HH * WW;

    // ---- per-pixel bilinear setup (invariant across channels) ----
    const float fx = flow[(((size_t)b * 2 + 0) * HH + h) * WW + w];
    const float fy = flow[(((size_t)b * 2 + 1) * HH + h) * WW + w];
    const float x = (float)w + fx;
    const float y = (float)h + fy;
    const float x0f = floorf(x);
    const float y0f = floorf(y);
    const int ix0 = (int)x0f;
    const int iy0 = (int)y0f;
    const float ax = x - x0f;
    const float ay = y - y0f;

    float w00 = (1.f - ax) * (1.f - ay);
    float w01 = ax * (1.f - ay);
    float w10 = (1.f - ax) * ay;
    float w11 = ax * ay;

    const bool vx0 = (ix0     >= 0) & (ix0     <= WW - 1);
    const bool vx1 = (ix0 + 1 >= 0) & (ix0 + 1 <= WW - 1);
    const bool vy0 = (iy0     >= 0) & (iy0     <= HH - 1);
    const bool vy1 = (iy0 + 1 >= 0) & (iy0 + 1 <= HH - 1);
    if (!(vx0 & vy0)) w00 = 0.f;
    if (!(vx1 & vy0)) w01 = 0.f;
    if (!(vx0 & vy1)) w10 = 0.f;
    if (!(vx1 & vy1)) w11 = 0.f;

    const int x0c = min(max(ix0, 0), WW - 1);
    const int x1c = min(max(ix0 + 1, 0), WW - 1);
    const int y0c = min(max(iy0, 0), HH - 1);
    const int y1c = min(max(iy0 + 1, 0), HH - 1);

    const int o00 = y0c * WW + x0c;
    const int o01 = y0c * WW + x1c;
    const int o10 = y1c * WW + x0c;
    const int o11 = y1c * WW + x1c;

    // phase-2 identity: pixel pair pg, channel-parity cs
    const int pg = t >> 1;
    const int cs = t & 1;

    float acc0[WIN], acc1[WIN];
#pragma unroll
    for (int k = 0; k < WIN; ++k) { acc0[k] = 0.f; acc1[k] = 0.f; }

    const size_t base_c0 = (size_t)(b * CC + g * CG) * HW;
    const float* lrow = left + base_c0 + (size_t)h * WW;  // + cc*HW + w

    for (int ch0 = 0; ch0 < CG; ch0 += CK) {
        __syncthreads();   // protect previous chunk's readers

        // ---- phase 1: bilinear warp + left staging (map: t -> w, coalesced) ----
#pragma unroll
        for (int cc = 0; cc < CK; ++cc) {
            const float* rb = right + base_c0 + (size_t)(ch0 + cc) * HW;
            float v = rb[o00] * w00;
            v = fmaf(rb[o01], w01, v);
            v = fmaf(rb[o10], w10, v);
            v = fmaf(rb[o11], w11, v);
            srw[cc][4 + w] = v;
            if (w == 0) {
                srw[cc][0] = v; srw[cc][1] = v; srw[cc][2] = v; srw[cc][3] = v;
            }
            if (w == WW - 1) {
                srw[cc][WW + 4] = v; srw[cc][WW + 5] = v;
                srw[cc][WW + 6] = v; srw[cc][WW + 7] = v;
            }
            slf[cc][w] = lrow[(size_t)(ch0 + cc) * HW + w];
        }
        __syncthreads();

        // ---- phase 2: pixel-pair correlation (map: (pg, cs)) ----
#pragma unroll
        for (int i = 0; i < CK / 2; ++i) {
            const int cc = 2 * i + cs;
            const float2 lv = *(const float2*)&slf[cc][2 * pg];
            float s[10];
#pragma unroll
            for (int j = 0; j < 5; ++j) {
                const float2 d = *(const float2*)&srw[cc][2 * pg + 2 * j];
                s[2 * j]     = d.x;
                s[2 * j + 1] = d.y;
            }
#pragma unroll
            for (int k = 0; k < WIN; ++k) {
                acc0[k] = fmaf(lv.x, s[k],     acc0[k]);
                acc1[k] = fmaf(lv.y, s[k + 1], acc1[k]);
            }
        }
    }

    // ---- merge channel-parity partials within each pixel pair ----
#pragma unroll
    for (int k = 0; k < WIN; ++k) {
        acc0[k] += __shfl_xor_sync(0xffffffffu, acc0[k], 1);
        acc1[k] += __shfl_xor_sync(0xffffffffu, acc1[k], 1);
    }

    // even thread writes pixel 2pg (acc0), odd thread writes pixel 2pg+1 (acc1).
    // wout == t, so stores are fully coalesced per tap.
    const float scale = 1.f / (float)CG;
    float* obase = out + (((size_t)(b * NGRP + g) * WIN) * HH + h) * WW + w;
#pragma unroll
    for (int k = 0; k < WIN; ++k) {
        const float v = (cs == 0) ? acc0[k] : acc1[k];
        obase[(size_t)k * HW] = v * scale;
    }
}

extern "C" void kernel_launch(void* const* d_in, const int* in_sizes, int n_in,
                              void* d_out, int out_size)
{
    const float* left  = (const float*)d_in[0];
    const float* right = (const float*)d_in[1];
    const float* flow  = (const float*)d_in[2];
    float* out = (float*)d_out;

    dim3 grid(BB * HH * NGRP);  // 2048 blocks: one per (b, h, group)
    dim3 block(WW);             // 256 threads
    crestereo_corr_kernel<<<grid, block>>>(left, right, flow, out);
}

// round 3
// speedup vs baseline: 1.1576x; 1.1576x over previous
#include <cuda_runtime.h>

// Fixed problem shape
#define BB   4
#define CC   256
#define HH   128
#define WW   256
#define NGRP 4
#define CG   64      // channels per group
#define WIN  9       // 1x9 window
#define CK   32      // channel chunk held in smem
#define SRS  264     // padded smem row: cols 0..263, pixel w lives at w+4 (replicate pad 4 each side)

__global__ __launch_bounds__(256, 4)
void crestereo_corr_kernel(const float* __restrict__ left,
                           const float* __restrict__ right,
                           const float* __restrict__ flow,
                           float* __restrict__ out)
{
    __shared__ float srw[CK][SRS];   // warped right row for current channel chunk

    const int bh = blockIdx.x;
    const int b  = bh >> 7;          // bh / HH
    const int h  = bh & (HH - 1);
    const int w  = threadIdx.x;
    const int HW = HH * WW;

    // ---- per-pixel bilinear setup (invariant across channels) ----
    const float fx = flow[(((size_t)b * 2 + 0) * HH + h) * WW + w];
    const float fy = flow[(((size_t)b * 2 + 1) * HH + h) * WW + w];
    const float x = (float)w + fx;
    const float y = (float)h + fy;
    const float x0f = floorf(x);
    const float y0f = floorf(y);
    const int ix0 = (int)x0f;
    const int iy0 = (int)y0f;
    const float ax = x - x0f;
    const float ay = y - y0f;

    float w00 = (1.f - ax) * (1.f - ay);
    float w01 = ax * (1.f - ay);
    float w10 = (1.f - ax) * ay;
    float w11 = ax * ay;

    const bool vx0 = (ix0     >= 0) & (ix0     <= WW - 1);
    const bool vx1 = (ix0 + 1 >= 0) & (ix0 + 1 <= WW - 1);
    const bool vy0 = (iy0     >= 0) & (iy0     <= HH - 1);
    const bool vy1 = (iy0 + 1 >= 0) & (iy0 + 1 <= HH - 1);
    if (!(vx0 & vy0)) w00 = 0.f;
    if (!(vx1 & vy0)) w01 = 0.f;
    if (!(vx0 & vy1)) w10 = 0.f;
    if (!(vx1 & vy1)) w11 = 0.f;

    const int x0c = min(max(ix0, 0), WW - 1);
    const int x1c = min(max(ix0 + 1, 0), WW - 1);
    const int y0c = min(max(iy0, 0), HH - 1);
    const int y1c = min(max(iy0 + 1, 0), HH - 1);

    const int o00 = y0c * WW + x0c;
    const int o01 = y0c * WW + x1c;
    const int o10 = y1c * WW + x0c;
    const int o11 = y1c * WW + x1c;

    const float* lbase = left  + (size_t)b * CC * HW + (size_t)h * WW + w;
    const float* rbase = right + (size_t)b * CC * HW;

    float acc[WIN];

    for (int g = 0; g < NGRP; ++g) {
#pragma unroll
        for (int k = 0; k < WIN; ++k) acc[k] = 0.f;

        for (int ch0 = g * CG; ch0 < (g + 1) * CG; ch0 += CK) {
            __syncthreads();   // protect previous chunk's readers

            // ---- phase 1: bilinear warp CK channels into padded smem row ----
#pragma unroll 4
            for (int cc = 0; cc < CK; ++cc) {
                const float* rb = rbase + (size_t)(ch0 + cc) * HW;
                float v = rb[o00] * w00;
                v = fmaf(rb[o01], w01, v);
                v = fmaf(rb[o10], w10, v);
                v = fmaf(rb[o11], w11, v);
                srw[cc][4 + w] = v;
                if (w == 0) {
                    srw[cc][0] = v; srw[cc][1] = v; srw[cc][2] = v; srw[cc][3] = v;
                }
                if (w == WW - 1) {
                    srw[cc][WW + 4] = v; srw[cc][WW + 5] = v;
                    srw[cc][WW + 6] = v; srw[cc][WW + 7] = v;
                }
            }
            __syncthreads();

            // ---- phase 2: 9-tap sliding-window accumulate (taps at sp[0..8]) ----
#pragma unroll 8
            for (int cc = 0; cc < CK; ++cc) {
                const float lv = lbase[(size_t)(ch0 + cc) * HW];
                const float* sp = &srw[cc][w];
#pragma unroll
                for (int k = 0; k < WIN; ++k)
                    acc[k] = fmaf(lv, sp[k], acc[k]);
            }
        }

        // ---- write 9 output taps for this group (coalesced across w) ----
        const float scale = 1.f / (float)CG;
        float* obase = out + (((size_t)(b * NGRP + g) * WIN) * HH + h) * WW + w;
#pragma unroll
        for (int k = 0; k < WIN; ++k)
            obase[(size_t)k * HW] = acc[k] * scale;
    }
}

extern "C" void kernel_launch(void* const* d_in, const int* in_sizes, int n_in,
                              void* d_out, int out_size)
{
    const float* left  = (const float*)d_in[0];
    const float* right = (const float*)d_in[1];
    const float* flow  = (const float*)d_in[2];
    float* out = (float*)d_out;

    dim3 grid(BB * HH);   // 512 blocks: one per (b, h) row
    dim3 block(WW);       // 256 threads
    crestereo_corr_kernel<<<grid, block>>>(left, right, flow, out);
}